// round 6
// baseline (speedup 1.0000x reference)
#include <cuda_runtime.h>

#define D_MODEL 2048
#define SEQ_L   256
#define BATCH_N 128
#define CHUNK   256           // channels per block (2 float4 columns per thread)

struct cf { float re, im; };
__device__ __forceinline__ cf cmulf(cf a, cf b) {
    return { a.re*b.re - a.im*b.im, a.re*b.im + a.im*b.re };
}
__device__ __forceinline__ cf caddf(cf a, cf b) { return { a.re + b.re, a.im + b.im }; }
__device__ __forceinline__ cf cdivf(cf a, cf b) {
    float inv = 1.0f / (b.re*b.re + b.im*b.im);
    return { (a.re*b.re + a.im*b.im)*inv, (a.im*b.re - a.re*b.im)*inv };
}

// Single fused kernel.
// Phase 1 (all 256 threads): fp32 taps for this block's 256 channels -> smem.
// Phase 2: t-major streaming conv. Warp w owns t in [w*32,(w+1)*32); each lane
//   owns TWO float4 columns (CHUNK=256). u[t-1] carried in registers.
//   One-shot stream -> __ldcs / __stcs (evict-first) to keep it out of L2's
//   retained set.
__global__ __launch_bounds__(256) void s4d_fused_kernel(
    const float* __restrict__ u,
    const float* __restrict__ A_real, const float* __restrict__ A_imag,
    const float* __restrict__ B_real, const float* __restrict__ B_imag,
    const float* __restrict__ C_real, const float* __restrict__ C_imag,
    const float* __restrict__ Dvec,
    float* __restrict__ out)
{
    __shared__ float s_g0[CHUNK];
    __shared__ float s_g1[CHUNK];

    const int tid    = threadIdx.x;
    const int chunk0 = blockIdx.x * CHUNK;

    {   // taps: one channel per thread (256 == CHUNK)
        const int d = chunk0 + tid;
        const float a0r = -expf(A_real[2*d]),   a0i = A_imag[2*d];
        const float a1r = -expf(A_real[2*d+1]), a1i = A_imag[2*d+1];

        cf p0 = cdivf({1.f + 0.5f*a0r,  0.5f*a0i},
                      {1.f - 0.5f*a0r, -0.5f*a0i});
        cf p1 = cdivf({1.f + 0.5f*a1r,  0.5f*a1i},
                      {1.f - 0.5f*a1r, -0.5f*a1i});

        cf m00 = p0, m01 = {-1.f, 0.f}, m11 = p1;
        #pragma unroll
        for (int s = 0; s < 8; s++) {           // M <- M^2 (symmetric), => M^256
            cf m01sq = cmulf(m01, m01);
            cf n00 = caddf(cmulf(m00, m00), m01sq);
            cf n01 = cmulf(m01, caddf(m00, m11));
            cf n11 = caddf(m01sq, cmulf(m11, m11));
            m00 = n00; m01 = n01; m11 = n11;
        }

        cf B0 = { B_real[2*d],   B_imag[2*d]   };
        cf B1 = { B_real[2*d+1], B_imag[2*d+1] };
        cf C0 = { C_real[2*d],   C_imag[2*d]   };
        cf C1 = { C_real[2*d+1], C_imag[2*d+1] };

        cf t0 = caddf(cmulf({1.f - m00.re, -m00.im}, B0),
                      cmulf({     -m01.re, -m01.im}, B1));
        cf t1 = caddf(cmulf({     -m01.re, -m01.im}, B0),
                      cmulf({1.f - m11.re, -m11.im}, B1));

        s_g0[tid] = (C0.re*t0.re - C0.im*t0.im) + Dvec[d];
        s_g1[tid] = (C1.re*t1.re - C1.im*t1.im);
    }
    __syncthreads();

    const int lane = tid & 31;
    const int w    = tid >> 5;
    const int t0i  = w * 32;

    // Column A: lanes cover [0,128) floats; column B: [128,256) of the chunk.
    const float4 g0a = *reinterpret_cast<const float4*>(s_g0 + lane*4);
    const float4 g1a = *reinterpret_cast<const float4*>(s_g1 + lane*4);
    const float4 g0b = *reinterpret_cast<const float4*>(s_g0 + 128 + lane*4);
    const float4 g1b = *reinterpret_cast<const float4*>(s_g1 + 128 + lane*4);

    const unsigned int base =
        ((unsigned int)blockIdx.y * SEQ_L + (unsigned int)t0i) * D_MODEL
        + (unsigned int)chunk0 + (unsigned int)lane * 4u;

    const float4* __restrict__ upA = reinterpret_cast<const float4*>(u + base);
    const float4* __restrict__ upB = reinterpret_cast<const float4*>(u + base + 128);
    float4*       __restrict__ opA = reinterpret_cast<float4*>(out + base);
    float4*       __restrict__ opB = reinterpret_cast<float4*>(out + base + 128);

    float4 upvA, upvB;
    if (t0i == 0) {
        upvA = make_float4(0.f, 0.f, 0.f, 0.f);
        upvB = upvA;
    } else {
        upvA = __ldcs(reinterpret_cast<const float4*>(u + base - D_MODEL));
        upvB = __ldcs(reinterpret_cast<const float4*>(u + base + 128 - D_MODEL));
    }

    #pragma unroll 8
    for (int k = 0; k < 32; k++) {
        const unsigned int off = (unsigned int)k * (D_MODEL/4);
        float4 uvA = __ldcs(upA + off);
        float4 uvB = __ldcs(upB + off);
        float4 oA, oB;
        oA.x = fmaf(g0a.x, uvA.x, g1a.x * upvA.x);
        oA.y = fmaf(g0a.y, uvA.y, g1a.y * upvA.y);
        oA.z = fmaf(g0a.z, uvA.z, g1a.z * upvA.z);
        oA.w = fmaf(g0a.w, uvA.w, g1a.w * upvA.w);
        oB.x = fmaf(g0b.x, uvB.x, g1b.x * upvB.x);
        oB.y = fmaf(g0b.y, uvB.y, g1b.y * upvB.y);
        oB.z = fmaf(g0b.z, uvB.z, g1b.z * upvB.z);
        oB.w = fmaf(g0b.w, uvB.w, g1b.w * upvB.w);
        __stcs(opA + off, oA);
        __stcs(opB + off, oB);
        upvA = uvA;
        upvB = uvB;
    }
}

extern "C" void kernel_launch(void* const* d_in, const int* in_sizes, int n_in,
                              void* d_out, int out_size) {
    const float* u      = (const float*)d_in[0];
    const float* A_real = (const float*)d_in[1];
    const float* A_imag = (const float*)d_in[2];
    const float* B_real = (const float*)d_in[3];
    const float* B_imag = (const float*)d_in[4];
    const float* C_real = (const float*)d_in[5];
    const float* C_imag = (const float*)d_in[6];
    const float* Dvec   = (const float*)d_in[7];
    float* out = (float*)d_out;

    dim3 grid(D_MODEL / CHUNK, BATCH_N);   // (8, 128) = 1024 blocks
    s4d_fused_kernel<<<grid, 256>>>(u, A_real, A_imag, B_real, B_imag,
                                    C_real, C_imag, Dvec, out);
}

// round 7
// speedup vs baseline: 1.0073x; 1.0073x over previous
#include <cuda_runtime.h>

#define D_MODEL 2048
#define SEQ_L   256
#define BATCH_N 128
#define CHUNK   128           // channels per block (R4-proven shape: regs 32, occ ~87%)

struct cf { float re, im; };
__device__ __forceinline__ cf cmulf(cf a, cf b) {
    return { a.re*b.re - a.im*b.im, a.re*b.im + a.im*b.re };
}
__device__ __forceinline__ cf caddf(cf a, cf b) { return { a.re + b.re, a.im + b.im }; }
__device__ __forceinline__ cf cdivf(cf a, cf b) {
    float inv = 1.0f / (b.re*b.re + b.im*b.im);
    return { (a.re*b.re + a.im*b.im)*inv, (a.im*b.re - a.re*b.im)*inv };
}

// Single fused kernel (R4 structure, + __stcs on write-once output stores).
// Phase 1 (threads 0..127): fp32 taps for this block's 128 channels -> smem.
// Phase 2 (all 256 threads): t-major streaming conv; warp w owns t in
//   [w*32,(w+1)*32), lane owns one float4 column. u[t-1] carried in a register.
__global__ __launch_bounds__(256) void s4d_fused_kernel(
    const float* __restrict__ u,
    const float* __restrict__ A_real, const float* __restrict__ A_imag,
    const float* __restrict__ B_real, const float* __restrict__ B_imag,
    const float* __restrict__ C_real, const float* __restrict__ C_imag,
    const float* __restrict__ Dvec,
    float* __restrict__ out)
{
    __shared__ float s_g0[CHUNK];
    __shared__ float s_g1[CHUNK];

    const int tid    = threadIdx.x;
    const int chunk0 = blockIdx.x * CHUNK;

    if (tid < CHUNK) {
        const int d = chunk0 + tid;
        const float a0r = -expf(A_real[2*d]),   a0i = A_imag[2*d];
        const float a1r = -expf(A_real[2*d+1]), a1i = A_imag[2*d+1];

        cf p0 = cdivf({1.f + 0.5f*a0r,  0.5f*a0i},
                      {1.f - 0.5f*a0r, -0.5f*a0i});
        cf p1 = cdivf({1.f + 0.5f*a1r,  0.5f*a1i},
                      {1.f - 0.5f*a1r, -0.5f*a1i});

        cf m00 = p0, m01 = {-1.f, 0.f}, m11 = p1;
        #pragma unroll
        for (int s = 0; s < 8; s++) {           // M <- M^2 (symmetric), => M^256
            cf m01sq = cmulf(m01, m01);
            cf n00 = caddf(cmulf(m00, m00), m01sq);
            cf n01 = cmulf(m01, caddf(m00, m11));
            cf n11 = caddf(m01sq, cmulf(m11, m11));
            m00 = n00; m01 = n01; m11 = n11;
        }

        cf B0 = { B_real[2*d],   B_imag[2*d]   };
        cf B1 = { B_real[2*d+1], B_imag[2*d+1] };
        cf C0 = { C_real[2*d],   C_imag[2*d]   };
        cf C1 = { C_real[2*d+1], C_imag[2*d+1] };

        cf t0 = caddf(cmulf({1.f - m00.re, -m00.im}, B0),
                      cmulf({     -m01.re, -m01.im}, B1));
        cf t1 = caddf(cmulf({     -m01.re, -m01.im}, B0),
                      cmulf({1.f - m11.re, -m11.im}, B1));

        s_g0[tid] = (C0.re*t0.re - C0.im*t0.im) + Dvec[d];
        s_g1[tid] = (C1.re*t1.re - C1.im*t1.im);
    }
    __syncthreads();

    const int lane = tid & 31;          // float4 column within chunk
    const int w    = tid >> 5;          // t-group
    const int t0i  = w * 32;

    const float4 g0 = *reinterpret_cast<const float4*>(s_g0 + lane*4);
    const float4 g1 = *reinterpret_cast<const float4*>(s_g1 + lane*4);

    const unsigned int base =
        ((unsigned int)blockIdx.y * SEQ_L + (unsigned int)t0i) * D_MODEL
        + (unsigned int)chunk0 + (unsigned int)lane * 4u;

    const float4* __restrict__ up = reinterpret_cast<const float4*>(u + base);
    float4*       __restrict__ op = reinterpret_cast<float4*>(out + base);

    float4 uprev;
    if (t0i == 0) uprev = make_float4(0.f, 0.f, 0.f, 0.f);
    else          uprev = *reinterpret_cast<const float4*>(u + base - D_MODEL);

    #pragma unroll 8
    for (int k = 0; k < 32; k++) {
        float4 uv = up[(unsigned int)k * (D_MODEL/4)];
        float4 o;
        o.x = fmaf(g0.x, uv.x, g1.x * uprev.x);
        o.y = fmaf(g0.y, uv.y, g1.y * uprev.y);
        o.z = fmaf(g0.z, uv.z, g1.z * uprev.z);
        o.w = fmaf(g0.w, uv.w, g1.w * uprev.w);
        __stcs(op + (unsigned int)k * (D_MODEL/4), o);   // write-once stream: evict-first
        uprev = uv;
    }
}

extern "C" void kernel_launch(void* const* d_in, const int* in_sizes, int n_in,
                              void* d_out, int out_size) {
    const float* u      = (const float*)d_in[0];
    const float* A_real = (const float*)d_in[1];
    const float* A_imag = (const float*)d_in[2];
    const float* B_real = (const float*)d_in[3];
    const float* B_imag = (const float*)d_in[4];
    const float* C_real = (const float*)d_in[5];
    const float* C_imag = (const float*)d_in[6];
    const float* Dvec   = (const float*)d_in[7];
    float* out = (float*)d_out;

    dim3 grid(D_MODEL / CHUNK, BATCH_N);   // (16, 128) = 2048 blocks
    s4d_fused_kernel<<<grid, 256>>>(u, A_real, A_imag, B_real, B_imag,
                                    C_real, C_imag, Dvec, out);
}